// round 15
// baseline (speedup 1.0000x reference)
#include <cuda_runtime.h>
#include <cuda_fp16.h>
#include <math.h>

#define B_   2
#define S_   2048
#define D_   1024
#define H_   16
#define DH_  64
#define M_   (B_*S_)          // 4096 tokens
#define BH_  (B_*H_)          // 32
#define KK_  512              // top-k
#define MCH_ 16               // mean chunks

#define SA   40               // smem row stride (halves) for 32-col tiles
#define SBP  136              // smem row stride for 128-col B tiles
#define SBV  72               // smem row stride for 64-col tiles (av)
#define QST  72               // scores kernel: Q/K row stride (64 cols + pad)

#define HG_ASTG (128*SA)      // 5120 halves per A stage
#define HG_BSTG (32*SBP)      // 4352 halves per B stage
#define HG_SMEM (3*(HG_ASTG+HG_BSTG)*(int)sizeof(__half))   // 56832 bytes

#define AV_ASTG (128*SBV)     // 9216 halves per attn stage (128 x 64)
#define AV_BSTG (64*SBV)      // 4608 halves per V stage (64 x 64)
#define AV_PAR  (128*12)      // per-row params
#define AV_SMEM (2*(AV_ASTG+AV_BSTG)*(int)sizeof(__half) + AV_PAR)  // 56832 bytes

// ---------------- scratch (static device memory; no allocations) ----------------
__device__ __half g_xh[M_*D_];
__device__ __half g_Wcat[D_*4*D_];         // packed [1024][4096] : Wq|Wk|Wv|Wg
__device__ float  g_bcat[4*D_];
__device__ __half g_Woh[D_*D_];
__device__ __half g_qkvgh[(size_t)M_*4*D_]; // [4096][4096] : q|k|v|gate
__device__ __half g_qnh[M_*D_];     // [BH][S][DH]
__device__ __half g_knh[M_*D_];     // [BH][S][DH]
__device__ __half g_vhh[M_*D_];     // [BH][S][DH]
__device__ __half g_obsdh[M_*D_];   // attention output in [B,S,D]
__device__ __half g_out2h[M_*D_];   // after Wo
__device__ __half g_scoresh[(size_t)BH_*S_*S_]; // 256MB fp16 scores (post-temp)
__device__ unsigned g_selT[BH_*S_]; // per-row threshold key
__device__ float  g_mxv[BH_*S_];    // per-row max
__device__ float  g_invv[BH_*S_];   // per-row 1/sum
__device__ float  g_xpart[MCH_*B_*D_];
__device__ float  g_xmean[B_*D_];
__device__ float  g_temp[B_];

// ---------------- mma / ldmatrix / cp.async helpers ----------------
__device__ __forceinline__ void mma_f16(float* d, const unsigned* a, unsigned b0, unsigned b1){
    asm volatile("mma.sync.aligned.m16n8k16.row.col.f32.f16.f16.f32 "
        "{%0,%1,%2,%3}, {%4,%5,%6,%7}, {%8,%9}, {%0,%1,%2,%3};\n"
        : "+f"(d[0]),"+f"(d[1]),"+f"(d[2]),"+f"(d[3])
        : "r"(a[0]),"r"(a[1]),"r"(a[2]),"r"(a[3]), "r"(b0),"r"(b1));
}
__device__ __forceinline__ void ldsm4(unsigned* r, const __half* p){
    unsigned addr = (unsigned)__cvta_generic_to_shared(p);
    asm volatile("ldmatrix.sync.aligned.m8n8.x4.shared.b16 {%0,%1,%2,%3}, [%4];\n"
        :"=r"(r[0]),"=r"(r[1]),"=r"(r[2]),"=r"(r[3]) : "r"(addr));
}
__device__ __forceinline__ void ldsm4t(unsigned* r, const __half* p){
    unsigned addr = (unsigned)__cvta_generic_to_shared(p);
    asm volatile("ldmatrix.sync.aligned.m8n8.x4.trans.shared.b16 {%0,%1,%2,%3}, [%4];\n"
        :"=r"(r[0]),"=r"(r[1]),"=r"(r[2]),"=r"(r[3]) : "r"(addr));
}
__device__ __forceinline__ void cp_async16(void* smem_ptr, const void* gptr){
    unsigned saddr = (unsigned)__cvta_generic_to_shared(smem_ptr);
    asm volatile("cp.async.cg.shared.global [%0], [%1], 16;\n" :: "r"(saddr), "l"(gptr));
}
__device__ __forceinline__ void cp_commit(){ asm volatile("cp.async.commit_group;\n" ::: "memory"); }
__device__ __forceinline__ void cp_wait1(){ asm volatile("cp.async.wait_group 1;\n" ::: "memory"); }
__device__ __forceinline__ void cp_wait0(){ asm volatile("cp.async.wait_group 0;\n" ::: "memory"); }

// ---------------- fp32 -> fp16 conversion ----------------
__global__ __launch_bounds__(256) void f2h_kernel(const float* __restrict__ in,
                                                  __half* __restrict__ out){
    int i = blockIdx.x*256 + threadIdx.x;
    float4 v = reinterpret_cast<const float4*>(in)[i];
    reinterpret_cast<__half2*>(out)[2*i]   = __floats2half2_rn(v.x, v.y);
    reinterpret_cast<__half2*>(out)[2*i+1] = __floats2half2_rn(v.z, v.w);
}

__global__ __launch_bounds__(256) void f2h_pack4(const float* __restrict__ w0,
                                                 const float* __restrict__ w1,
                                                 const float* __restrict__ w2,
                                                 const float* __restrict__ w3){
    int gi = blockIdx.x*256 + threadIdx.x;
    int q = gi >> 18;
    int i = gi & 262143;
    const float* in = (q==0) ? w0 : (q==1) ? w1 : (q==2) ? w2 : w3;
    int row = i >> 8, c4 = (i & 255) * 4;
    float4 v = reinterpret_cast<const float4*>(in)[i];
    __half* o = g_Wcat + (size_t)row*4096 + q*1024 + c4;
    *(__half2*)&o[0] = __floats2half2_rn(v.x, v.y);
    *(__half2*)&o[2] = __floats2half2_rn(v.z, v.w);
}

__global__ __launch_bounds__(256) void pack_bias(const float* __restrict__ bq,
                                                 const float* __restrict__ bk,
                                                 const float* __restrict__ bv,
                                                 const float* __restrict__ bg){
    int idx = blockIdx.x*256 + threadIdx.x;
    int seg = idx >> 10, j = idx & 1023;
    float v = (seg==0) ? bq[j] : (seg==1) ? bk[j] : (seg==2) ? bv[j] : bg[j];
    g_bcat[idx] = v;
}

// ---------------- mean over sequence + temperature ----------------
__global__ __launch_bounds__(256) void mean_stage1(const float* __restrict__ x){
    int b  = blockIdx.x / MCH_;
    int ch = blockIdx.x % MCH_;
    int s0 = ch * (S_/MCH_);
    int tid = threadIdx.x;
    float acc[4] = {0.f,0.f,0.f,0.f};
    for (int s = s0; s < s0 + S_/MCH_; ++s){
        const float* xp = x + ((size_t)(b*S_+s))*D_;
        #pragma unroll
        for (int j = 0; j < 4; ++j) acc[j] += xp[tid + j*256];
    }
    #pragma unroll
    for (int j = 0; j < 4; ++j) g_xpart[((size_t)ch*B_ + b)*D_ + tid + j*256] = acc[j];
}

__global__ __launch_bounds__(256) void mean_stage2(){
    int idx = blockIdx.x*256 + threadIdx.x;
    int b = idx / D_, d = idx % D_;
    float s = 0.f;
    #pragma unroll
    for (int ch = 0; ch < MCH_; ++ch) s += g_xpart[((size_t)ch*B_ + b)*D_ + d];
    g_xmean[idx] = s * (1.0f/S_);
}

__global__ __launch_bounds__(256) void temp_kernel(const float* __restrict__ Wt,
                                                   const float* __restrict__ bt){
    __shared__ float red[256];
    int b = blockIdx.x, tid = threadIdx.x;
    float s = 0.f;
    for (int d = tid; d < D_; d += 256) s += g_xmean[b*D_ + d] * Wt[d];
    red[tid] = s; __syncthreads();
    for (int o = 128; o; o >>= 1){ if (tid < o) red[tid] += red[tid+o]; __syncthreads(); }
    if (tid == 0) g_temp[b] = 1.0f/(1.0f + expf(-(red[0] + bt[0]))) + 0.5f;
}

// ---------------- fp16 tensor-core GEMM: 64x64 warp tiles, 3-stage cp.async ----------------
// RACE FIX (r15): final iteration must wait for ALL groups (its own tile is the
// only outstanding one and wait_group 1 would NOT wait for it).
__global__ __launch_bounds__(128) void hgemm_bias(const __half* __restrict__ A,
                                                  const __half* __restrict__ Bw,
                                                  const float* __restrict__ bias,
                                                  __half* __restrict__ C,
                                                  int M, int N, int K){
    extern __shared__ __half hsm[];
    __half* As = hsm;
    __half* Bs = hsm + 3*HG_ASTG;
    const int tid = threadIdx.x, lane = tid & 31, wid = tid >> 5;
    const int m0 = blockIdx.y*128, n0 = blockIdx.x*128;
    const int wm = (wid & 1)*64, wn = (wid >> 1)*64;
    const int KT = K >> 5;
    float acc[4][8][4] = {};

    #define HG_LOAD(stage, k0)                                                   \
        {                                                                        \
            __half* as = As + (stage)*HG_ASTG;                                   \
            __half* bs = Bs + (stage)*HG_BSTG;                                   \
            _Pragma("unroll")                                                    \
            for (int j = 0; j < 4; ++j){                                         \
                int idx = j*128 + tid;                                           \
                int rowA = idx >> 2, cA = (idx & 3) << 3;                        \
                cp_async16(&as[rowA*SA + cA], A + (size_t)(m0+rowA)*K + (k0) + cA); \
                int rowB = idx >> 4, cB = (idx & 15) << 3;                       \
                cp_async16(&bs[rowB*SBP + cB], Bw + (size_t)((k0)+rowB)*N + n0 + cB); \
            }                                                                    \
            cp_commit();                                                         \
        }

    HG_LOAD(0, 0)
    HG_LOAD(1, 32)

    for (int kt = 0; kt < KT; ++kt){
        const int cur = kt % 3;
        if (kt == KT-1) cp_wait0();   // last tile: wait for everything (RACE FIX)
        else            cp_wait1();
        __syncthreads();
        __half* as = As + cur*HG_ASTG;
        __half* bs = Bs + cur*HG_BSTG;
        #pragma unroll
        for (int ks = 0; ks < 2; ++ks){
            unsigned af[4][4], bf[4][4];
            #pragma unroll
            for (int mt = 0; mt < 4; ++mt)
                ldsm4(af[mt], &as[(wm+mt*16+(lane&15))*SA + ks*16 + (lane>>4)*8]);
            #pragma unroll
            for (int g = 0; g < 4; ++g)
                ldsm4t(bf[g], &bs[(ks*16+(lane&15))*SBP + wn + g*16 + (lane>>4)*8]);
            #pragma unroll
            for (int mt = 0; mt < 4; ++mt)
                #pragma unroll
                for (int g = 0; g < 4; ++g){
                    mma_f16(acc[mt][2*g],   af[mt], bf[g][0], bf[g][1]);
                    mma_f16(acc[mt][2*g+1], af[mt], bf[g][2], bf[g][3]);
                }
        }
        if (kt+2 < KT){
            HG_LOAD((kt+2) % 3, (kt+2)*32)
        }
    }
    #undef HG_LOAD

    #pragma unroll
    for (int mt = 0; mt < 4; ++mt){
        int r = m0 + wm + mt*16 + (lane >> 2);
        #pragma unroll
        for (int nt = 0; nt < 8; ++nt){
            int c = n0 + wn + nt*8 + (lane & 3)*2;
            float b0 = bias[c], b1 = bias[c+1];
            *(__half2*)&C[(size_t)r*N + c] =
                __floats2half2_rn(acc[mt][nt][0]+b0, acc[mt][nt][1]+b1);
            *(__half2*)&C[(size_t)(r+8)*N + c] =
                __floats2half2_rn(acc[mt][nt][2]+b0, acc[mt][nt][3]+b1);
        }
    }
}

// ---------------- head split + L2 normalize (q,k) + v relayout (from qkvg) ----------------
__global__ __launch_bounds__(256) void norm_split(){
    int gw   = (blockIdx.x*256 + threadIdx.x) >> 5;
    int lane = threadIdx.x & 31;
    int s  = gw & (S_-1);
    int bh = gw >> 11;
    int h  = bh & (H_-1), b = bh >> 4;
    size_t row = (size_t)(b*S_+s)*4096;
    int hc = h*DH_ + lane*2;
    size_t dst = (size_t)gw * DH_ + lane*2;

    float2 qv = __half22float2(*(const __half2*)(g_qkvgh + row + hc));
    float ss = qv.x*qv.x + qv.y*qv.y;
    #pragma unroll
    for (int o = 16; o; o >>= 1) ss += __shfl_xor_sync(0xFFFFFFFFu, ss, o);
    float inv = 1.0f / fmaxf(sqrtf(ss), 1e-12f);
    *(__half2*)(g_qnh + dst) = __floats2half2_rn(qv.x*inv, qv.y*inv);

    float2 kv = __half22float2(*(const __half2*)(g_qkvgh + row + 1024 + hc));
    ss = kv.x*kv.x + kv.y*kv.y;
    #pragma unroll
    for (int o = 16; o; o >>= 1) ss += __shfl_xor_sync(0xFFFFFFFFu, ss, o);
    inv = 1.0f / fmaxf(sqrtf(ss), 1e-12f);
    *(__half2*)(g_knh + dst) = __floats2half2_rn(kv.x*inv, kv.y*inv);

    *(__half2*)(g_vhh + dst) = *(const __half2*)(g_qkvgh + row + 2048 + hc);
}

// ---------------- scores v2: one block = 128 rows x full 2048 keys ----------------
__global__ __launch_bounds__(256) void scores_mma(){
    extern __shared__ __half sm[];
    __half* Qs  = sm;                     // 128 x QST
    __half* Ksb = sm + 128*QST;           // 2 x 128 x QST
    const int bh = blockIdx.y, b = bh >> 4;
    const int m0 = blockIdx.x * 128;
    const __half* Qg = g_qnh + (size_t)bh*S_*DH_;
    const __half* Kg = g_knh + (size_t)bh*S_*DH_;
    const int tid = threadIdx.x, lane = tid & 31, wid = tid >> 5;
    const int wm = (wid & 1)*64, wn = (wid >> 1)*32;

    #pragma unroll
    for (int j = 0; j < 4; ++j){
        int idx = j*256 + tid;
        int row = idx >> 3, c8 = (idx & 7) << 3;
        *(float4*)&Qs[row*QST + c8] = *(const float4*)(Qg + (size_t)(m0+row)*DH_ + c8);
        *(float4*)&Ksb[row*QST + c8] = *(const float4*)(Kg + (size_t)row*DH_ + c8);
    }
    __syncthreads();

    unsigned af[4][4][4];
    #pragma unroll
    for (int ks = 0; ks < 4; ++ks)
        #pragma unroll
        for (int mt = 0; mt < 4; ++mt)
            ldsm4(af[ks][mt], &Qs[(wm+mt*16+(lane&15))*QST + ks*16 + (lane>>4)*8]);

    const float scl = 1.0f / g_temp[b];

    for (int c = 0; c < 16; ++c){
        __half* cur = Ksb + (c & 1)*(128*QST);
        __half* nb  = Ksb + ((c+1) & 1)*(128*QST);
        float4 pre[4];
        const bool nxt = (c+1 < 16);
        if (nxt){
            #pragma unroll
            for (int j = 0; j < 4; ++j){
                int idx = j*256 + tid;
                int row = idx >> 3, c8 = (idx & 7) << 3;
                pre[j] = *(const float4*)(Kg + (size_t)((c+1)*128+row)*DH_ + c8);
            }
        }
        float acc[4][4][4] = {};
        #pragma unroll
        for (int ks = 0; ks < 4; ++ks){
            unsigned bf[2][4];
            #pragma unroll
            for (int g = 0; g < 2; ++g)
                ldsm4(bf[g], &cur[(wn + g*16 + ((lane>>4)<<3) + (lane&7))*QST
                                  + ks*16 + ((lane>>3)&1)*8]);
            #pragma unroll
            for (int mt = 0; mt < 4; ++mt)
                #pragma unroll
                for (int g = 0; g < 2; ++g){
                    mma_f16(acc[mt][2*g],   af[ks][mt], bf[g][0], bf[g][1]);
                    mma_f16(acc[mt][2*g+1], af[ks][mt], bf[g][2], bf[g][3]);
                }
        }
        #pragma unroll
        for (int mt = 0; mt < 4; ++mt){
            int r = m0 + wm + mt*16 + (lane >> 2);
            #pragma unroll
            for (int nt = 0; nt < 4; ++nt){
                int col = c*128 + wn + nt*8 + (lane & 3)*2;
                *(__half2*)&g_scoresh[((size_t)bh*S_ + r)*S_ + col] =
                    __floats2half2_rn(acc[mt][nt][0]*scl, acc[mt][nt][1]*scl);
                *(__half2*)&g_scoresh[((size_t)bh*S_ + r + 8)*S_ + col] =
                    __floats2half2_rn(acc[mt][nt][2]*scl, acc[mt][nt][3]*scl);
            }
        }
        if (nxt){
            __syncthreads();
            #pragma unroll
            for (int j = 0; j < 4; ++j){
                int idx = j*256 + tid;
                int row = idx >> 3, c8 = (idx & 7) << 3;
                *(float4*)&nb[row*QST + c8] = pre[j];
            }
            __syncthreads();
        }
    }
}

// ---------------- top-512 select: emit per-row {T, mx, inv} only ----------------
__global__ __launch_bounds__(256) void topk_params(){
    const size_t row = blockIdx.x;
    const __half* sp = g_scoresh + row*(size_t)S_;
    __shared__ unsigned hist[256];
    __shared__ unsigned sufs[256];
    __shared__ unsigned wsum[8];
    __shared__ float fr[8];
    __shared__ unsigned s_bin, s_above;
    __shared__ float s_mx;
    const int tid = threadIdx.x, lane = tid & 31, wid = tid >> 5;

    int4 raw = *(const int4*)(sp + (size_t)tid*8);
    unsigned rw[4] = {(unsigned)raw.x, (unsigned)raw.y, (unsigned)raw.z, (unsigned)raw.w};
    float v[8]; unsigned key[8];
    #pragma unroll
    for (int i = 0; i < 8; ++i){
        unsigned u = (rw[i>>1] >> ((i&1)*16)) & 0xFFFFu;
        v[i] = __half2float(__ushort_as_half((unsigned short)u));
        key[i] = u ^ ((u & 0x8000u) ? 0xFFFFu : 0x8000u);
    }

    unsigned prefix = 0, remaining = KK_;
    #pragma unroll
    for (int pass = 0; pass < 2; ++pass){
        const int shift = 8 - pass*8;
        hist[tid] = 0; __syncthreads();
        unsigned pmask = (pass == 0) ? 0u : 0xFF00u;
        #pragma unroll
        for (int i = 0; i < 8; ++i)
            if ((key[i] & pmask) == prefix) atomicAdd(&hist[(key[i] >> shift) & 255], 1u);
        __syncthreads();
        unsigned x = hist[255 - tid];
        #pragma unroll
        for (int o = 1; o < 32; o <<= 1){
            unsigned t = __shfl_up_sync(0xFFFFFFFFu, x, o);
            if (lane >= o) x += t;
        }
        if (lane == 31) wsum[wid] = x;
        __syncthreads();
        if (tid < 8){
            unsigned w = wsum[tid];
            #pragma unroll
            for (int o = 1; o < 8; o <<= 1){
                unsigned t = __shfl_up_sync(0xFFu, w, o);
                if (tid >= o) w += t;
            }
            wsum[tid] = w;
        }
        __syncthreads();
        unsigned suf = x + (wid ? wsum[wid-1] : 0u);
        sufs[255 - tid] = suf;
        __syncthreads();
        unsigned Sb  = sufs[tid];
        unsigned Sb1 = (tid < 255) ? sufs[tid+1] : 0u;
        if (Sb >= remaining && Sb1 < remaining){ s_bin = (unsigned)tid; s_above = Sb1; }
        __syncthreads();
        remaining -= s_above;
        prefix |= (s_bin << shift);
        __syncthreads();
    }
    const unsigned T = prefix;

    float mx = -3.402823466e38f;
    #pragma unroll
    for (int i = 0; i < 8; ++i) mx = fmaxf(mx, v[i]);
    #pragma unroll
    for (int o = 16; o; o >>= 1) mx = fmaxf(mx, __shfl_xor_sync(0xFFFFFFFFu, mx, o));
    if (lane == 0) fr[wid] = mx;
    __syncthreads();
    if (tid == 0){
        float m = fr[0];
        #pragma unroll
        for (int j = 1; j < 8; ++j) m = fmaxf(m, fr[j]);
        s_mx = m;
    }
    __syncthreads();
    mx = s_mx;

    float ls = 0.f;
    #pragma unroll
    for (int i = 0; i < 8; ++i)
        if (key[i] >= T) ls += expf(v[i] - mx);
    #pragma unroll
    for (int o = 16; o; o >>= 1) ls += __shfl_xor_sync(0xFFFFFFFFu, ls, o);
    if (lane == 0) fr[wid] = ls;
    __syncthreads();
    if (tid == 0){
        float m = 0.f;
        #pragma unroll
        for (int j = 0; j < 8; ++j) m += fr[j];
        g_selT[row] = T;
        g_mxv[row]  = mx;
        g_invv[row] = 1.0f / m;
    }
}

// ---------------- O = attn @ V : reads SCORES, materializes weights in smem ----------------
// BM=128, BN=64, BK=64, 8 warps (4M x 2N), 2-stage cp.async (wait0 each iter: race-free)
__global__ __launch_bounds__(256) void av_mma(){
    extern __shared__ __half avsm[];
    __half* As = avsm;                   // 2 stages x 128*SBV
    __half* Bs = avsm + 2*AV_ASTG;       // 2 stages x 64*SBV
    float*  pmx  = (float*)(avsm + 2*(AV_ASTG+AV_BSTG));
    float*  pinv = pmx + 128;
    unsigned* pT = (unsigned*)(pinv + 128);
    const int bh = blockIdx.z;
    const int m0 = blockIdx.y*128;
    const __half* A = g_scoresh + (size_t)bh*S_*S_;
    const __half* V = g_vhh    + (size_t)bh*S_*DH_;
    const int tid = threadIdx.x, lane = tid & 31, wid = tid >> 5;
    const int wm = (wid & 3)*32, wn = (wid >> 2)*32;
    float acc[2][4][4] = {};

    if (tid < 128){
        int gr = bh*S_ + m0 + tid;
        pmx[tid]  = g_mxv[gr];
        pinv[tid] = g_invv[gr];
        pT[tid]   = g_selT[gr];
    }

    #define AV_LOAD(stage, k0)                                                    \
        {                                                                         \
            __half* as = As + (stage)*AV_ASTG;                                    \
            __half* bs = Bs + (stage)*AV_BSTG;                                    \
            _Pragma("unroll")                                                     \
            for (int j = 0; j < 4; ++j){                                          \
                int idx = j*256 + tid;                                            \
                int row = idx >> 3, c8 = (idx & 7) << 3;                          \
                cp_async16(&as[row*SBV + c8], A + (size_t)(m0+row)*S_ + (k0) + c8); \
            }                                                                     \
            _Pragma("unroll")                                                     \
            for (int j = 0; j < 2; ++j){                                          \
                int idx = j*256 + tid;                                            \
                int row = idx >> 3, c8 = (idx & 7) << 3;                          \
                cp_async16(&bs[row*SBV + c8], V + (size_t)((k0)+row)*DH_ + c8);   \
            }                                                                     \
            cp_commit();                                                          \
        }

    AV_LOAD(0, 0)

    const int KT = S_ >> 6;   // 32
    for (int kt = 0; kt < KT; ++kt){
        const int cur = kt & 1;
        cp_wait0();
        __syncthreads();    // stage data + params visible
        if (kt+1 < KT){
            AV_LOAD(cur^1, (kt+1)*64)
        }
        __half* as = As + cur*AV_ASTG;
        __half* bs = Bs + cur*AV_BSTG;
        // transform scores -> weights in place (same math as topk's old write pass)
        #pragma unroll
        for (int j = 0; j < 4; ++j){
            int idx = j*256 + tid;
            int row = idx >> 3, c8 = (idx & 7) << 3;
            const float mx = pmx[row], inv = pinv[row];
            const unsigned T = pT[row];
            uint4 r4 = *(uint4*)&as[row*SBV + c8];
            unsigned rwv[4] = {r4.x, r4.y, r4.z, r4.w};
            #pragma unroll
            for (int q = 0; q < 4; ++q){
                unsigned u0 = rwv[q] & 0xFFFFu;
                unsigned u1 = rwv[q] >> 16;
                unsigned k0k = u0 ^ ((u0 & 0x8000u) ? 0xFFFFu : 0x8000u);
                unsigned k1k = u1 ^ ((u1 & 0x8000u) ? 0xFFFFu : 0x8000u);
                float w0 = (k0k >= T)
                    ? expf(__half2float(__ushort_as_half((unsigned short)u0)) - mx)*inv : 0.0f;
                float w1 = (k1k >= T)
                    ? expf(__half2float(__ushort_as_half((unsigned short)u1)) - mx)*inv : 0.0f;
                __half2 p = __floats2half2_rn(w0, w1);
                rwv[q] = *(unsigned*)&p;
            }
            *(uint4*)&as[row*SBV + c8] = make_uint4(rwv[0], rwv[1], rwv[2], rwv[3]);
        }
        __syncthreads();    // weights materialized before ldsm
        #pragma unroll
        for (int ks = 0; ks < 4; ++ks){
            unsigned af[2][4], bf[2][4];
            #pragma unroll
            for (int mt = 0; mt < 2; ++mt)
                ldsm4(af[mt], &as[(wm+mt*16+(lane&15))*SBV + ks*16 + (lane>>4)*8]);
            #pragma unroll
            for (int g = 0; g < 2; ++g)
                ldsm4t(bf[g], &bs[(ks*16+(lane&15))*SBV + wn + g*16 + (lane>>4)*8]);
            #pragma unroll
            for (int mt = 0; mt < 2; ++mt)
                #pragma unroll
                for (int g = 0; g < 2; ++g){
                    mma_f16(acc[mt][2*g],   af[mt], bf[g][0], bf[g][1]);
                    mma_f16(acc[mt][2*g+1], af[mt], bf[g][2], bf[g][3]);
                }
        }
    }
    #undef AV_LOAD

    const int bb = bh >> 4, h = bh & (H_-1);
    #pragma unroll
    for (int mt = 0; mt < 2; ++mt){
        int s_idx = m0 + wm + mt*16 + (lane >> 2);
        size_t grow0 = (size_t)(bb*S_ + s_idx)*D_;
        size_t grow1 = (size_t)(bb*S_ + s_idx + 8)*D_;
        #pragma unroll
        for (int nt = 0; nt < 4; ++nt){
            int c = h*DH_ + wn + nt*8 + (lane & 3)*2;
            *(__half2*)&g_obsdh[grow0 + c] = __floats2half2_rn(acc[mt][nt][0], acc[mt][nt][1]);
            *(__half2*)&g_obsdh[grow1 + c] = __floats2half2_rn(acc[mt][nt][2], acc[mt][nt][3]);
        }
    }
}

// ---------------- highway gating ----------------
__global__ __launch_bounds__(256) void finalize_kernel(const float* __restrict__ x,
                                                       float* __restrict__ out){
    int i = blockIdx.x*256 + threadIdx.x;
    int p = 2*i;
    int r = p >> 10, cb = p & 1023;
    float2 xv = reinterpret_cast<const float2*>(x)[i];
    float2 gv = __half22float2(*(const __half2*)&g_qkvgh[(size_t)r*4096 + 3072 + cb]);
    float2 ov = __half22float2(reinterpret_cast<const __half2*>(g_out2h)[i]);
    float2 rr;
    float g;
    g = 1.0f/(1.0f+expf(-gv.x)); rr.x = g*ov.x + (1.0f-g)*xv.x;
    g = 1.0f/(1.0f+expf(-gv.y)); rr.y = g*ov.y + (1.0f-g)*xv.y;
    reinterpret_cast<float2*>(out)[i] = rr;
}

// ---------------- launch ----------------
extern "C" void kernel_launch(void* const* d_in, const int* in_sizes, int n_in,
                              void* d_out, int out_size){
    (void)in_sizes; (void)n_in; (void)out_size;
    const float* x  = (const float*)d_in[0];
    const float* Wq = (const float*)d_in[1];  const float* bq = (const float*)d_in[2];
    const float* Wk = (const float*)d_in[3];  const float* bk = (const float*)d_in[4];
    const float* Wv = (const float*)d_in[5];  const float* bv = (const float*)d_in[6];
    const float* Wo = (const float*)d_in[7];  const float* bo = (const float*)d_in[8];
    const float* Wt = (const float*)d_in[9];  const float* bt = (const float*)d_in[10];
    const float* Wg = (const float*)d_in[11]; const float* bg = (const float*)d_in[12];
    float* out = (float*)d_out;

    __half *xh,*Wcat,*Woh,*qkvgh,*obsdh,*out2h;
    float *bcat;
    cudaGetSymbolAddress((void**)&xh,    g_xh);
    cudaGetSymbolAddress((void**)&Wcat,  g_Wcat);
    cudaGetSymbolAddress((void**)&bcat,  g_bcat);
    cudaGetSymbolAddress((void**)&Woh,   g_Woh);
    cudaGetSymbolAddress((void**)&qkvgh, g_qkvgh);
    cudaGetSymbolAddress((void**)&obsdh, g_obsdh);
    cudaGetSymbolAddress((void**)&out2h, g_out2h);

    const int SC_SMEM = 3*128*QST*(int)sizeof(__half);   // 55296 bytes
    cudaFuncSetAttribute(scores_mma, cudaFuncAttributeMaxDynamicSharedMemorySize, SC_SMEM);
    cudaFuncSetAttribute(hgemm_bias, cudaFuncAttributeMaxDynamicSharedMemorySize, HG_SMEM);
    cudaFuncSetAttribute(av_mma,     cudaFuncAttributeMaxDynamicSharedMemorySize, AV_SMEM);

    pack_bias<<<16, 256>>>(bq, bk, bv, bg);                        // 0
    f2h_kernel<<<(M_*D_)/1024, 256>>>(x, xh);                      // 1
    f2h_pack4<<<4*(D_*D_)/1024, 256>>>(Wq, Wk, Wv, Wg);            // 2

    // launch 3: fused QKVG projection (profiled by ncu)
    hgemm_bias<<<dim3(4096/128, M_/128), 128, HG_SMEM>>>(xh, Wcat, bcat, qkvgh, M_, 4096, D_);

    f2h_kernel<<<(D_*D_)/1024, 256>>>(Wo, Woh);

    // temperature path (fp32)
    mean_stage1<<<B_*MCH_, 256>>>(x);
    mean_stage2<<<(B_*D_)/256, 256>>>();
    temp_kernel<<<B_, 256>>>(Wt, bt);

    // normalize + head relayout
    norm_split<<<(BH_*S_*32)/256, 256>>>();

    // scores, per-row top-k params, attn @ V (weights materialized in-kernel)
    scores_mma<<<dim3(S_/128, BH_), 256, SC_SMEM>>>();
    topk_params<<<BH_*S_, 256>>>();
    av_mma<<<dim3(1, S_/128, BH_), 256, AV_SMEM>>>();

    // output projection + highway gate
    hgemm_bias<<<dim3(D_/128, M_/128), 128, HG_SMEM>>>(obsdh, Woh, bo, out2h, M_, D_, D_);
    finalize_kernel<<<(M_*D_/2)/256, 256>>>(x, out);
}

// round 16
// speedup vs baseline: 1.1684x; 1.1684x over previous
#include <cuda_runtime.h>
#include <cuda_fp16.h>
#include <math.h>

#define B_   2
#define S_   2048
#define D_   1024
#define H_   16
#define DH_  64
#define M_   (B_*S_)          // 4096 tokens
#define BH_  (B_*H_)          // 32
#define KK_  512              // top-k
#define MCH_ 16               // mean chunks

#define SA   40               // smem row stride (halves) for 32-col tiles
#define SBP  136              // smem row stride for 128-col B tiles
#define SBV  72               // smem row stride for 64-col tiles (av)
#define QST  72               // scores kernel: Q/K row stride (64 cols + pad)

#define HG_ASTG (128*SA)      // 5120 halves per A stage
#define HG_BSTG (32*SBP)      // 4352 halves per B stage
#define HG_SMEM (3*(HG_ASTG+HG_BSTG)*(int)sizeof(__half))   // 56832 bytes

#define AV_ASTG (128*SBV)     // 9216 halves per attn stage (128 x 64)
#define AV_BSTG (64*SBV)      // 4608 halves per V stage (64 x 64)
#define AV_SMEM (3*(AV_ASTG+AV_BSTG)*(int)sizeof(__half))   // 82944 bytes

// ---------------- scratch (static device memory; no allocations) ----------------
__device__ __half g_xh[M_*D_];
__device__ __half g_Wcat[D_*4*D_];         // packed [1024][4096] : Wq|Wk|Wv|Wg
__device__ float  g_bcat[4*D_];
__device__ __half g_Woh[D_*D_];
__device__ __half g_qkvgh[(size_t)M_*4*D_]; // [4096][4096] : q|k|v|gate
__device__ __half g_qnh[M_*D_];     // [BH][S][DH]
__device__ __half g_knh[M_*D_];     // [BH][S][DH]
__device__ __half g_vhh[M_*D_];     // [BH][S][DH]
__device__ __half g_obsdh[M_*D_];   // attention output in [B,S,D]
__device__ __half g_out2h[M_*D_];   // after Wo
__device__ __half g_scoresh[(size_t)BH_*S_*S_]; // 256MB fp16 scores (post-temp)
__device__ __half g_attnh[(size_t)BH_*S_*S_];   // 256MB fp16 attention weights
__device__ float  g_xpart[MCH_*B_*D_];
__device__ float  g_xmean[B_*D_];
__device__ float  g_temp[B_];

// ---------------- mma / ldmatrix / cp.async helpers ----------------
__device__ __forceinline__ void mma_f16(float* d, const unsigned* a, unsigned b0, unsigned b1){
    asm volatile("mma.sync.aligned.m16n8k16.row.col.f32.f16.f16.f32 "
        "{%0,%1,%2,%3}, {%4,%5,%6,%7}, {%8,%9}, {%0,%1,%2,%3};\n"
        : "+f"(d[0]),"+f"(d[1]),"+f"(d[2]),"+f"(d[3])
        : "r"(a[0]),"r"(a[1]),"r"(a[2]),"r"(a[3]), "r"(b0),"r"(b1));
}
__device__ __forceinline__ void ldsm4(unsigned* r, const __half* p){
    unsigned addr = (unsigned)__cvta_generic_to_shared(p);
    asm volatile("ldmatrix.sync.aligned.m8n8.x4.shared.b16 {%0,%1,%2,%3}, [%4];\n"
        :"=r"(r[0]),"=r"(r[1]),"=r"(r[2]),"=r"(r[3]) : "r"(addr));
}
__device__ __forceinline__ void ldsm4t(unsigned* r, const __half* p){
    unsigned addr = (unsigned)__cvta_generic_to_shared(p);
    asm volatile("ldmatrix.sync.aligned.m8n8.x4.trans.shared.b16 {%0,%1,%2,%3}, [%4];\n"
        :"=r"(r[0]),"=r"(r[1]),"=r"(r[2]),"=r"(r[3]) : "r"(addr));
}
__device__ __forceinline__ void cp_async16(void* smem_ptr, const void* gptr){
    unsigned saddr = (unsigned)__cvta_generic_to_shared(smem_ptr);
    asm volatile("cp.async.cg.shared.global [%0], [%1], 16;\n" :: "r"(saddr), "l"(gptr));
}
__device__ __forceinline__ void cp_commit(){ asm volatile("cp.async.commit_group;\n" ::: "memory"); }
__device__ __forceinline__ void cp_wait1(){ asm volatile("cp.async.wait_group 1;\n" ::: "memory"); }
__device__ __forceinline__ void cp_wait0(){ asm volatile("cp.async.wait_group 0;\n" ::: "memory"); }

// ---------------- fp32 -> fp16 conversion ----------------
__global__ __launch_bounds__(256) void f2h_kernel(const float* __restrict__ in,
                                                  __half* __restrict__ out){
    int i = blockIdx.x*256 + threadIdx.x;
    float4 v = reinterpret_cast<const float4*>(in)[i];
    reinterpret_cast<__half2*>(out)[2*i]   = __floats2half2_rn(v.x, v.y);
    reinterpret_cast<__half2*>(out)[2*i+1] = __floats2half2_rn(v.z, v.w);
}

__global__ __launch_bounds__(256) void f2h_pack4(const float* __restrict__ w0,
                                                 const float* __restrict__ w1,
                                                 const float* __restrict__ w2,
                                                 const float* __restrict__ w3){
    int gi = blockIdx.x*256 + threadIdx.x;
    int q = gi >> 18;
    int i = gi & 262143;
    const float* in = (q==0) ? w0 : (q==1) ? w1 : (q==2) ? w2 : w3;
    int row = i >> 8, c4 = (i & 255) * 4;
    float4 v = reinterpret_cast<const float4*>(in)[i];
    __half* o = g_Wcat + (size_t)row*4096 + q*1024 + c4;
    *(__half2*)&o[0] = __floats2half2_rn(v.x, v.y);
    *(__half2*)&o[2] = __floats2half2_rn(v.z, v.w);
}

__global__ __launch_bounds__(256) void pack_bias(const float* __restrict__ bq,
                                                 const float* __restrict__ bk,
                                                 const float* __restrict__ bv,
                                                 const float* __restrict__ bg){
    int idx = blockIdx.x*256 + threadIdx.x;
    int seg = idx >> 10, j = idx & 1023;
    float v = (seg==0) ? bq[j] : (seg==1) ? bk[j] : (seg==2) ? bv[j] : bg[j];
    g_bcat[idx] = v;
}

// ---------------- mean over sequence + temperature ----------------
__global__ __launch_bounds__(256) void mean_stage1(const float* __restrict__ x){
    int b  = blockIdx.x / MCH_;
    int ch = blockIdx.x % MCH_;
    int s0 = ch * (S_/MCH_);
    int tid = threadIdx.x;
    float acc[4] = {0.f,0.f,0.f,0.f};
    for (int s = s0; s < s0 + S_/MCH_; ++s){
        const float* xp = x + ((size_t)(b*S_+s))*D_;
        #pragma unroll
        for (int j = 0; j < 4; ++j) acc[j] += xp[tid + j*256];
    }
    #pragma unroll
    for (int j = 0; j < 4; ++j) g_xpart[((size_t)ch*B_ + b)*D_ + tid + j*256] = acc[j];
}

__global__ __launch_bounds__(256) void mean_stage2(){
    int idx = blockIdx.x*256 + threadIdx.x;
    int b = idx / D_, d = idx % D_;
    float s = 0.f;
    #pragma unroll
    for (int ch = 0; ch < MCH_; ++ch) s += g_xpart[((size_t)ch*B_ + b)*D_ + d];
    g_xmean[idx] = s * (1.0f/S_);
}

__global__ __launch_bounds__(256) void temp_kernel(const float* __restrict__ Wt,
                                                   const float* __restrict__ bt){
    __shared__ float red[256];
    int b = blockIdx.x, tid = threadIdx.x;
    float s = 0.f;
    for (int d = tid; d < D_; d += 256) s += g_xmean[b*D_ + d] * Wt[d];
    red[tid] = s; __syncthreads();
    for (int o = 128; o; o >>= 1){ if (tid < o) red[tid] += red[tid+o]; __syncthreads(); }
    if (tid == 0) g_temp[b] = 1.0f/(1.0f + expf(-(red[0] + bt[0]))) + 0.5f;
}

// ---------------- fp16 tensor-core GEMM: 64x64 warp tiles, 3-stage cp.async (race-fixed) ----------------
__global__ __launch_bounds__(128) void hgemm_bias(const __half* __restrict__ A,
                                                  const __half* __restrict__ Bw,
                                                  const float* __restrict__ bias,
                                                  __half* __restrict__ C,
                                                  int M, int N, int K){
    extern __shared__ __half hsm[];
    __half* As = hsm;
    __half* Bs = hsm + 3*HG_ASTG;
    const int tid = threadIdx.x, lane = tid & 31, wid = tid >> 5;
    const int m0 = blockIdx.y*128, n0 = blockIdx.x*128;
    const int wm = (wid & 1)*64, wn = (wid >> 1)*64;
    const int KT = K >> 5;
    float acc[4][8][4] = {};

    #define HG_LOAD(stage, k0)                                                   \
        {                                                                        \
            __half* as = As + (stage)*HG_ASTG;                                   \
            __half* bs = Bs + (stage)*HG_BSTG;                                   \
            _Pragma("unroll")                                                    \
            for (int j = 0; j < 4; ++j){                                         \
                int idx = j*128 + tid;                                           \
                int rowA = idx >> 2, cA = (idx & 3) << 3;                        \
                cp_async16(&as[rowA*SA + cA], A + (size_t)(m0+rowA)*K + (k0) + cA); \
                int rowB = idx >> 4, cB = (idx & 15) << 3;                       \
                cp_async16(&bs[rowB*SBP + cB], Bw + (size_t)((k0)+rowB)*N + n0 + cB); \
            }                                                                    \
            cp_commit();                                                         \
        }

    HG_LOAD(0, 0)
    HG_LOAD(1, 32)

    for (int kt = 0; kt < KT; ++kt){
        const int cur = kt % 3;
        if (kt == KT-1) cp_wait0();   // final tile: wait for everything (race fix)
        else            cp_wait1();
        __syncthreads();
        __half* as = As + cur*HG_ASTG;
        __half* bs = Bs + cur*HG_BSTG;
        #pragma unroll
        for (int ks = 0; ks < 2; ++ks){
            unsigned af[4][4], bf[4][4];
            #pragma unroll
            for (int mt = 0; mt < 4; ++mt)
                ldsm4(af[mt], &as[(wm+mt*16+(lane&15))*SA + ks*16 + (lane>>4)*8]);
            #pragma unroll
            for (int g = 0; g < 4; ++g)
                ldsm4t(bf[g], &bs[(ks*16+(lane&15))*SBP + wn + g*16 + (lane>>4)*8]);
            #pragma unroll
            for (int mt = 0; mt < 4; ++mt)
                #pragma unroll
                for (int g = 0; g < 4; ++g){
                    mma_f16(acc[mt][2*g],   af[mt], bf[g][0], bf[g][1]);
                    mma_f16(acc[mt][2*g+1], af[mt], bf[g][2], bf[g][3]);
                }
        }
        if (kt+2 < KT){
            HG_LOAD((kt+2) % 3, (kt+2)*32)
        }
    }
    #undef HG_LOAD

    #pragma unroll
    for (int mt = 0; mt < 4; ++mt){
        int r = m0 + wm + mt*16 + (lane >> 2);
        #pragma unroll
        for (int nt = 0; nt < 8; ++nt){
            int c = n0 + wn + nt*8 + (lane & 3)*2;
            float b0 = bias[c], b1 = bias[c+1];
            *(__half2*)&C[(size_t)r*N + c] =
                __floats2half2_rn(acc[mt][nt][0]+b0, acc[mt][nt][1]+b1);
            *(__half2*)&C[(size_t)(r+8)*N + c] =
                __floats2half2_rn(acc[mt][nt][2]+b0, acc[mt][nt][3]+b1);
        }
    }
}

// ---------------- head split + L2 normalize (q,k) + v relayout (from qkvg) ----------------
__global__ __launch_bounds__(256) void norm_split(){
    int gw   = (blockIdx.x*256 + threadIdx.x) >> 5;
    int lane = threadIdx.x & 31;
    int s  = gw & (S_-1);
    int bh = gw >> 11;
    int h  = bh & (H_-1), b = bh >> 4;
    size_t row = (size_t)(b*S_+s)*4096;
    int hc = h*DH_ + lane*2;
    size_t dst = (size_t)gw * DH_ + lane*2;

    float2 qv = __half22float2(*(const __half2*)(g_qkvgh + row + hc));
    float ss = qv.x*qv.x + qv.y*qv.y;
    #pragma unroll
    for (int o = 16; o; o >>= 1) ss += __shfl_xor_sync(0xFFFFFFFFu, ss, o);
    float inv = 1.0f / fmaxf(sqrtf(ss), 1e-12f);
    *(__half2*)(g_qnh + dst) = __floats2half2_rn(qv.x*inv, qv.y*inv);

    float2 kv = __half22float2(*(const __half2*)(g_qkvgh + row + 1024 + hc));
    ss = kv.x*kv.x + kv.y*kv.y;
    #pragma unroll
    for (int o = 16; o; o >>= 1) ss += __shfl_xor_sync(0xFFFFFFFFu, ss, o);
    inv = 1.0f / fmaxf(sqrtf(ss), 1e-12f);
    *(__half2*)(g_knh + dst) = __floats2half2_rn(kv.x*inv, kv.y*inv);

    *(__half2*)(g_vhh + dst) = *(const __half2*)(g_qkvgh + row + 2048 + hc);
}

// ---------------- scores v2: one block = 128 rows x full 2048 keys ----------------
__global__ __launch_bounds__(256) void scores_mma(){
    extern __shared__ __half sm[];
    __half* Qs  = sm;                     // 128 x QST
    __half* Ksb = sm + 128*QST;           // 2 x 128 x QST
    const int bh = blockIdx.y, b = bh >> 4;
    const int m0 = blockIdx.x * 128;
    const __half* Qg = g_qnh + (size_t)bh*S_*DH_;
    const __half* Kg = g_knh + (size_t)bh*S_*DH_;
    const int tid = threadIdx.x, lane = tid & 31, wid = tid >> 5;
    const int wm = (wid & 1)*64, wn = (wid >> 1)*32;

    #pragma unroll
    for (int j = 0; j < 4; ++j){
        int idx = j*256 + tid;
        int row = idx >> 3, c8 = (idx & 7) << 3;
        *(float4*)&Qs[row*QST + c8] = *(const float4*)(Qg + (size_t)(m0+row)*DH_ + c8);
        *(float4*)&Ksb[row*QST + c8] = *(const float4*)(Kg + (size_t)row*DH_ + c8);
    }
    __syncthreads();

    unsigned af[4][4][4];
    #pragma unroll
    for (int ks = 0; ks < 4; ++ks)
        #pragma unroll
        for (int mt = 0; mt < 4; ++mt)
            ldsm4(af[ks][mt], &Qs[(wm+mt*16+(lane&15))*QST + ks*16 + (lane>>4)*8]);

    const float scl = 1.0f / g_temp[b];

    for (int c = 0; c < 16; ++c){
        __half* cur = Ksb + (c & 1)*(128*QST);
        __half* nb  = Ksb + ((c+1) & 1)*(128*QST);
        float4 pre[4];
        const bool nxt = (c+1 < 16);
        if (nxt){
            #pragma unroll
            for (int j = 0; j < 4; ++j){
                int idx = j*256 + tid;
                int row = idx >> 3, c8 = (idx & 7) << 3;
                pre[j] = *(const float4*)(Kg + (size_t)((c+1)*128+row)*DH_ + c8);
            }
        }
        float acc[4][4][4] = {};
        #pragma unroll
        for (int ks = 0; ks < 4; ++ks){
            unsigned bf[2][4];
            #pragma unroll
            for (int g = 0; g < 2; ++g)
                ldsm4(bf[g], &cur[(wn + g*16 + ((lane>>4)<<3) + (lane&7))*QST
                                  + ks*16 + ((lane>>3)&1)*8]);
            #pragma unroll
            for (int mt = 0; mt < 4; ++mt)
                #pragma unroll
                for (int g = 0; g < 2; ++g){
                    mma_f16(acc[mt][2*g],   af[ks][mt], bf[g][0], bf[g][1]);
                    mma_f16(acc[mt][2*g+1], af[ks][mt], bf[g][2], bf[g][3]);
                }
        }
        #pragma unroll
        for (int mt = 0; mt < 4; ++mt){
            int r = m0 + wm + mt*16 + (lane >> 2);
            #pragma unroll
            for (int nt = 0; nt < 4; ++nt){
                int col = c*128 + wn + nt*8 + (lane & 3)*2;
                *(__half2*)&g_scoresh[((size_t)bh*S_ + r)*S_ + col] =
                    __floats2half2_rn(acc[mt][nt][0]*scl, acc[mt][nt][1]*scl);
                *(__half2*)&g_scoresh[((size_t)bh*S_ + r + 8)*S_ + col] =
                    __floats2half2_rn(acc[mt][nt][2]*scl, acc[mt][nt][3]*scl);
            }
        }
        if (nxt){
            __syncthreads();
            #pragma unroll
            for (int j = 0; j < 4; ++j){
                int idx = j*256 + tid;
                int row = idx >> 3, c8 = (idx & 7) << 3;
                *(float4*)&nb[row*QST + c8] = pre[j];
            }
            __syncthreads();
        }
    }
}

// ---------------- exact top-512 radix-select (16-bit, 2 passes) + softmax -> weights ----------------
__global__ __launch_bounds__(256) void topk_softmax(){
    const size_t row = blockIdx.x;
    const __half* sp = g_scoresh + row*(size_t)S_;
    __half* ap = g_attnh + row*(size_t)S_;
    __shared__ unsigned hist[256];
    __shared__ unsigned sufs[256];
    __shared__ unsigned wsum[8];
    __shared__ float fr[8];
    __shared__ unsigned s_bin, s_above;
    __shared__ float s_mx, s_sum;
    const int tid = threadIdx.x, lane = tid & 31, wid = tid >> 5;

    int4 raw = *(const int4*)(sp + (size_t)tid*8);
    unsigned rw[4] = {(unsigned)raw.x, (unsigned)raw.y, (unsigned)raw.z, (unsigned)raw.w};
    float v[8]; unsigned key[8];
    #pragma unroll
    for (int i = 0; i < 8; ++i){
        unsigned u = (rw[i>>1] >> ((i&1)*16)) & 0xFFFFu;
        v[i] = __half2float(__ushort_as_half((unsigned short)u));
        key[i] = u ^ ((u & 0x8000u) ? 0xFFFFu : 0x8000u);
    }

    unsigned prefix = 0, remaining = KK_;
    #pragma unroll
    for (int pass = 0; pass < 2; ++pass){
        const int shift = 8 - pass*8;
        hist[tid] = 0; __syncthreads();
        unsigned pmask = (pass == 0) ? 0u : 0xFF00u;
        #pragma unroll
        for (int i = 0; i < 8; ++i)
            if ((key[i] & pmask) == prefix) atomicAdd(&hist[(key[i] >> shift) & 255], 1u);
        __syncthreads();
        unsigned x = hist[255 - tid];
        #pragma unroll
        for (int o = 1; o < 32; o <<= 1){
            unsigned t = __shfl_up_sync(0xFFFFFFFFu, x, o);
            if (lane >= o) x += t;
        }
        if (lane == 31) wsum[wid] = x;
        __syncthreads();
        if (tid < 8){
            unsigned w = wsum[tid];
            #pragma unroll
            for (int o = 1; o < 8; o <<= 1){
                unsigned t = __shfl_up_sync(0xFFu, w, o);
                if (tid >= o) w += t;
            }
            wsum[tid] = w;
        }
        __syncthreads();
        unsigned suf = x + (wid ? wsum[wid-1] : 0u);
        sufs[255 - tid] = suf;
        __syncthreads();
        unsigned Sb  = sufs[tid];
        unsigned Sb1 = (tid < 255) ? sufs[tid+1] : 0u;
        if (Sb >= remaining && Sb1 < remaining){ s_bin = (unsigned)tid; s_above = Sb1; }
        __syncthreads();
        remaining -= s_above;
        prefix |= (s_bin << shift);
        __syncthreads();
    }
    const unsigned T = prefix;

    float mx = -3.402823466e38f;
    #pragma unroll
    for (int i = 0; i < 8; ++i) mx = fmaxf(mx, v[i]);
    #pragma unroll
    for (int o = 16; o; o >>= 1) mx = fmaxf(mx, __shfl_xor_sync(0xFFFFFFFFu, mx, o));
    if (lane == 0) fr[wid] = mx;
    __syncthreads();
    if (tid == 0){
        float m = fr[0];
        #pragma unroll
        for (int j = 1; j < 8; ++j) m = fmaxf(m, fr[j]);
        s_mx = m;
    }
    __syncthreads();
    mx = s_mx;

    float e[8]; float ls = 0.f;
    #pragma unroll
    for (int i = 0; i < 8; ++i){
        e[i] = (key[i] >= T) ? expf(v[i] - mx) : 0.0f;
        ls += e[i];
    }
    #pragma unroll
    for (int o = 16; o; o >>= 1) ls += __shfl_xor_sync(0xFFFFFFFFu, ls, o);
    if (lane == 0) fr[wid] = ls;
    __syncthreads();
    if (tid == 0){
        float m = 0.f;
        #pragma unroll
        for (int j = 0; j < 8; ++j) m += fr[j];
        s_sum = m;
    }
    __syncthreads();
    const float inv = 1.0f / s_sum;

    unsigned ow[4];
    #pragma unroll
    for (int i = 0; i < 4; ++i){
        __half2 p = __floats2half2_rn(e[2*i]*inv, e[2*i+1]*inv);
        ow[i] = *(unsigned*)&p;
    }
    int4 o; o.x = (int)ow[0]; o.y = (int)ow[1]; o.z = (int)ow[2]; o.w = (int)ow[3];
    *(int4*)(ap + (size_t)tid*8) = o;
}

// ---------------- O = attn @ V : BK=64, 3-stage cp.async (race-aware waits) ----------------
// BM=128, BN=64, 8 warps (4M x 2N), KT=32
__global__ __launch_bounds__(256) void av_mma(){
    extern __shared__ __half avsm[];
    __half* As = avsm;                   // 3 stages x 128*SBV
    __half* Bs = avsm + 3*AV_ASTG;       // 3 stages x 64*SBV
    const int bh = blockIdx.z;
    const int m0 = blockIdx.y*128;
    const __half* A = g_attnh + (size_t)bh*S_*S_;
    const __half* V = g_vhh   + (size_t)bh*S_*DH_;
    const int tid = threadIdx.x, lane = tid & 31, wid = tid >> 5;
    const int wm = (wid & 3)*32, wn = (wid >> 2)*32;
    float acc[2][4][4] = {};

    #define AV_LOAD(stage, k0)                                                    \
        {                                                                         \
            __half* as = As + (stage)*AV_ASTG;                                    \
            __half* bs = Bs + (stage)*AV_BSTG;                                    \
            _Pragma("unroll")                                                     \
            for (int j = 0; j < 4; ++j){                                          \
                int idx = j*256 + tid;                                            \
                int row = idx >> 3, c8 = (idx & 7) << 3;                          \
                cp_async16(&as[row*SBV + c8], A + (size_t)(m0+row)*S_ + (k0) + c8); \
            }                                                                     \
            _Pragma("unroll")                                                     \
            for (int j = 0; j < 2; ++j){                                          \
                int idx = j*256 + tid;                                            \
                int row = idx >> 3, c8 = (idx & 7) << 3;                          \
                cp_async16(&bs[row*SBV + c8], V + (size_t)((k0)+row)*DH_ + c8);   \
            }                                                                     \
            cp_commit();                                                          \
        }

    AV_LOAD(0, 0)
    AV_LOAD(1, 64)

    const int KT = S_ >> 6;   // 32
    for (int kt = 0; kt < KT; ++kt){
        const int cur = kt % 3;
        if (kt == KT-1) cp_wait0();   // final tile: wait for everything
        else            cp_wait1();
        __syncthreads();
        __half* as = As + cur*AV_ASTG;
        __half* bs = Bs + cur*AV_BSTG;
        #pragma unroll
        for (int ks = 0; ks < 4; ++ks){
            unsigned af[2][4], bf[2][4];
            #pragma unroll
            for (int mt = 0; mt < 2; ++mt)
                ldsm4(af[mt], &as[(wm+mt*16+(lane&15))*SBV + ks*16 + (lane>>4)*8]);
            #pragma unroll
            for (int g = 0; g < 2; ++g)
                ldsm4t(bf[g], &bs[(ks*16+(lane&15))*SBV + wn + g*16 + (lane>>4)*8]);
            #pragma unroll
            for (int mt = 0; mt < 2; ++mt)
                #pragma unroll
                for (int g = 0; g < 2; ++g){
                    mma_f16(acc[mt][2*g],   af[mt], bf[g][0], bf[g][1]);
                    mma_f16(acc[mt][2*g+1], af[mt], bf[g][2], bf[g][3]);
                }
        }
        if (kt+2 < KT){
            AV_LOAD((kt+2) % 3, (kt+2)*64)
        }
    }
    #undef AV_LOAD

    const int bb = bh >> 4, h = bh & (H_-1);
    #pragma unroll
    for (int mt = 0; mt < 2; ++mt){
        int s_idx = m0 + wm + mt*16 + (lane >> 2);
        size_t grow0 = (size_t)(bb*S_ + s_idx)*D_;
        size_t grow1 = (size_t)(bb*S_ + s_idx + 8)*D_;
        #pragma unroll
        for (int nt = 0; nt < 4; ++nt){
            int c = h*DH_ + wn + nt*8 + (lane & 3)*2;
            *(__half2*)&g_obsdh[grow0 + c] = __floats2half2_rn(acc[mt][nt][0], acc[mt][nt][1]);
            *(__half2*)&g_obsdh[grow1 + c] = __floats2half2_rn(acc[mt][nt][2], acc[mt][nt][3]);
        }
    }
}

// ---------------- highway gating ----------------
__global__ __launch_bounds__(256) void finalize_kernel(const float* __restrict__ x,
                                                       float* __restrict__ out){
    int i = blockIdx.x*256 + threadIdx.x;
    int p = 2*i;
    int r = p >> 10, cb = p & 1023;
    float2 xv = reinterpret_cast<const float2*>(x)[i];
    float2 gv = __half22float2(*(const __half2*)&g_qkvgh[(size_t)r*4096 + 3072 + cb]);
    float2 ov = __half22float2(reinterpret_cast<const __half2*>(g_out2h)[i]);
    float2 rr;
    float g;
    g = 1.0f/(1.0f+expf(-gv.x)); rr.x = g*ov.x + (1.0f-g)*xv.x;
    g = 1.0f/(1.0f+expf(-gv.y)); rr.y = g*ov.y + (1.0f-g)*xv.y;
    reinterpret_cast<float2*>(out)[i] = rr;
}

// ---------------- launch ----------------
extern "C" void kernel_launch(void* const* d_in, const int* in_sizes, int n_in,
                              void* d_out, int out_size){
    (void)in_sizes; (void)n_in; (void)out_size;
    const float* x  = (const float*)d_in[0];
    const float* Wq = (const float*)d_in[1];  const float* bq = (const float*)d_in[2];
    const float* Wk = (const float*)d_in[3];  const float* bk = (const float*)d_in[4];
    const float* Wv = (const float*)d_in[5];  const float* bv = (const float*)d_in[6];
    const float* Wo = (const float*)d_in[7];  const float* bo = (const float*)d_in[8];
    const float* Wt = (const float*)d_in[9];  const float* bt = (const float*)d_in[10];
    const float* Wg = (const float*)d_in[11]; const float* bg = (const float*)d_in[12];
    float* out = (float*)d_out;

    __half *xh,*Wcat,*Woh,*qkvgh,*obsdh,*out2h;
    float *bcat;
    cudaGetSymbolAddress((void**)&xh,    g_xh);
    cudaGetSymbolAddress((void**)&Wcat,  g_Wcat);
    cudaGetSymbolAddress((void**)&bcat,  g_bcat);
    cudaGetSymbolAddress((void**)&Woh,   g_Woh);
    cudaGetSymbolAddress((void**)&qkvgh, g_qkvgh);
    cudaGetSymbolAddress((void**)&obsdh, g_obsdh);
    cudaGetSymbolAddress((void**)&out2h, g_out2h);

    const int SC_SMEM = 3*128*QST*(int)sizeof(__half);   // 55296 bytes
    cudaFuncSetAttribute(scores_mma, cudaFuncAttributeMaxDynamicSharedMemorySize, SC_SMEM);
    cudaFuncSetAttribute(hgemm_bias, cudaFuncAttributeMaxDynamicSharedMemorySize, HG_SMEM);
    cudaFuncSetAttribute(av_mma,     cudaFuncAttributeMaxDynamicSharedMemorySize, AV_SMEM);

    pack_bias<<<16, 256>>>(bq, bk, bv, bg);                        // 0
    f2h_kernel<<<(M_*D_)/1024, 256>>>(x, xh);                      // 1
    f2h_pack4<<<4*(D_*D_)/1024, 256>>>(Wq, Wk, Wv, Wg);            // 2

    // launch 3: fused QKVG projection (profiled by ncu)
    hgemm_bias<<<dim3(4096/128, M_/128), 128, HG_SMEM>>>(xh, Wcat, bcat, qkvgh, M_, 4096, D_);

    f2h_kernel<<<(D_*D_)/1024, 256>>>(Wo, Woh);

    // temperature path (fp32)
    mean_stage1<<<B_*MCH_, 256>>>(x);
    mean_stage2<<<(B_*D_)/256, 256>>>();
    temp_kernel<<<B_, 256>>>(Wt, bt);

    // normalize + head relayout
    norm_split<<<(BH_*S_*32)/256, 256>>>();

    // scores, top-k softmax (writes weights), attn @ V (3-stage pipelined)
    scores_mma<<<dim3(S_/128, BH_), 256, SC_SMEM>>>();
    topk_softmax<<<BH_*S_, 256>>>();
    av_mma<<<dim3(1, S_/128, BH_), 256, AV_SMEM>>>();

    // output projection + highway gate
    hgemm_bias<<<dim3(D_/128, M_/128), 128, HG_SMEM>>>(obsdh, Woh, bo, out2h, M_, D_, D_);
    finalize_kernel<<<(M_*D_/2)/256, 256>>>(x, out);
}